// round 1
// baseline (speedup 1.0000x reference)
#include <cuda_runtime.h>

// CRPS loss:
//   term1 = mean_i |s_i - y|                         (per pixel)
//   term2 = 0.5 * mean_{i,j} |s_i - s_j|
//         = sum_{i<j} |s_i - s_j| / (N*N)            (per pixel)
//   out   = mean over pixels of (term1 - term2)
//
// samples: [16, 4, 1, 256, 256] f32  -> 16 planes of 262144 contiguous floats
// target:  [4, 1, 256, 256]     f32  -> 262144 floats

#define NS     16
#define NPIX   (4 * 1 * 256 * 256)   // 262144
#define NVEC   (NPIX / 4)            // 65536 float4 work items
#define BLOCKS 256
#define THREADS 256

__device__ float g_partial[BLOCKS];

__device__ __forceinline__ float crps_pixel(const float* __restrict__ s, float y) {
    float t1 = 0.0f;
#pragma unroll
    for (int i = 0; i < NS; i++) {
        t1 += fabsf(s[i] - y);
    }
    float t2 = 0.0f;
#pragma unroll
    for (int i = 0; i < NS; i++) {
#pragma unroll
        for (int j = i + 1; j < NS; j++) {
            t2 += fabsf(s[i] - s[j]);
        }
    }
    return t1 * (1.0f / NS) - t2 * (1.0f / (NS * NS));
}

__global__ __launch_bounds__(THREADS) void crps_main_kernel(
    const float* __restrict__ samples,
    const float* __restrict__ target)
{
    const int v = blockIdx.x * THREADS + threadIdx.x;   // float4 index, 0..NVEC-1

    // Load target float4 and 16 sample float4s (coalesced, high MLP).
    const float4 t4 = reinterpret_cast<const float4*>(target)[v];
    float4 sv[NS];
#pragma unroll
    for (int i = 0; i < NS; i++) {
        sv[i] = reinterpret_cast<const float4*>(samples + (size_t)i * NPIX)[v];
    }

    float acc = 0.0f;
    float a[NS];

#pragma unroll
    for (int i = 0; i < NS; i++) a[i] = sv[i].x;
    acc += crps_pixel(a, t4.x);
#pragma unroll
    for (int i = 0; i < NS; i++) a[i] = sv[i].y;
    acc += crps_pixel(a, t4.y);
#pragma unroll
    for (int i = 0; i < NS; i++) a[i] = sv[i].z;
    acc += crps_pixel(a, t4.z);
#pragma unroll
    for (int i = 0; i < NS; i++) a[i] = sv[i].w;
    acc += crps_pixel(a, t4.w);

    // Block tree reduction.
    __shared__ float red[THREADS];
    red[threadIdx.x] = acc;
    __syncthreads();
#pragma unroll
    for (int off = THREADS / 2; off >= 32; off >>= 1) {
        if (threadIdx.x < off) red[threadIdx.x] += red[threadIdx.x + off];
        __syncthreads();
    }
    if (threadIdx.x < 32) {
        float w = red[threadIdx.x];
#pragma unroll
        for (int off = 16; off > 0; off >>= 1)
            w += __shfl_down_sync(0xFFFFFFFFu, w, off);
        if (threadIdx.x == 0) g_partial[blockIdx.x] = w;
    }
}

__global__ __launch_bounds__(BLOCKS) void crps_final_kernel(float* __restrict__ out)
{
    __shared__ float red[BLOCKS];
    red[threadIdx.x] = g_partial[threadIdx.x];
    __syncthreads();
#pragma unroll
    for (int off = BLOCKS / 2; off >= 32; off >>= 1) {
        if (threadIdx.x < off) red[threadIdx.x] += red[threadIdx.x + off];
        __syncthreads();
    }
    if (threadIdx.x < 32) {
        float w = red[threadIdx.x];
#pragma unroll
        for (int off = 16; off > 0; off >>= 1)
            w += __shfl_down_sync(0xFFFFFFFFu, w, off);
        if (threadIdx.x == 0) out[0] = w * (1.0f / NPIX);
    }
}

extern "C" void kernel_launch(void* const* d_in, const int* in_sizes, int n_in,
                              void* d_out, int out_size)
{
    const float* samples = (const float*)d_in[0];  // [16, 4, 1, 256, 256]
    const float* target  = (const float*)d_in[1];  // [4, 1, 256, 256]
    float* out = (float*)d_out;

    crps_main_kernel<<<BLOCKS, THREADS>>>(samples, target);
    crps_final_kernel<<<1, BLOCKS>>>(out);
}

// round 3
// speedup vs baseline: 2.0363x; 2.0363x over previous
#include <cuda_runtime.h>

// CRPS loss, fused single-kernel version.
//   term1 = mean_i |s_i - y|
//   term2 = sum_{i<j} |s_i - s_j| / 256
//   out   = mean over pixels (term1 - term2)
//
// samples: [16, 4, 1, 256, 256] f32 -> 16 planes of 262144 floats
// target:  [4, 1, 256, 256]     f32 -> 262144 floats

#define NS      16
#define NPIX    (4 * 1 * 256 * 256)     // 262144
#define THREADS 256
#define BLOCKS  (NPIX / THREADS)        // 1024

__device__ float        g_partial[BLOCKS];
__device__ unsigned int g_done = 0;     // reset to 0 by last block each run

__global__ __launch_bounds__(THREADS) void crps_fused_kernel(
    const float* __restrict__ samples,
    const float* __restrict__ target,
    float* __restrict__ out)
{
    const int tid = threadIdx.x;
    const int p   = blockIdx.x * THREADS + tid;     // pixel index

    // ---- per-pixel CRPS, scalar loads (no register blowup, no spills) ----
    float s[NS];
#pragma unroll
    for (int i = 0; i < NS; i++)
        s[i] = samples[(size_t)i * NPIX + p];
    const float y = target[p];

    // term1: 2 accumulators
    float t1a = 0.0f, t1b = 0.0f;
#pragma unroll
    for (int i = 0; i < NS; i += 2) {
        t1a += fabsf(s[i]     - y);
        t1b += fabsf(s[i + 1] - y);
    }

    // term2: 120 pairs, 4 interleaved accumulators to break the dep chain
    float t2[4] = {0.0f, 0.0f, 0.0f, 0.0f};
    {
        int c = 0;
#pragma unroll
        for (int i = 0; i < NS; i++) {
#pragma unroll
            for (int j = i + 1; j < NS; j++) {
                t2[c & 3] += fabsf(s[i] - s[j]);
                c++;
            }
        }
    }

    float val = (t1a + t1b) * (1.0f / NS)
              - ((t2[0] + t2[1]) + (t2[2] + t2[3])) * (1.0f / (NS * NS));

    // ---- block reduction (warp shfl -> smem -> warp 0) ----
    __shared__ float warp_sum[THREADS / 32];
    float w = val;
#pragma unroll
    for (int off = 16; off > 0; off >>= 1)
        w += __shfl_down_sync(0xFFFFFFFFu, w, off);
    if ((tid & 31) == 0) warp_sum[tid >> 5] = w;
    __syncthreads();

    __shared__ bool is_last;
    if (tid == 0) {
        float b = 0.0f;
#pragma unroll
        for (int k = 0; k < THREADS / 32; k++) b += warp_sum[k];
        g_partial[blockIdx.x] = b;
        __threadfence();
        unsigned int ticket = atomicAdd(&g_done, 1u);
        is_last = (ticket == BLOCKS - 1);
    }
    __syncthreads();

    // ---- last block folds all partials and writes the scalar ----
    if (is_last) {
        float acc = 0.0f;
#pragma unroll
        for (int k = 0; k < BLOCKS / THREADS; k++)
            acc += g_partial[tid + k * THREADS];
#pragma unroll
        for (int off = 16; off > 0; off >>= 1)
            acc += __shfl_down_sync(0xFFFFFFFFu, acc, off);
        if ((tid & 31) == 0) warp_sum[tid >> 5] = acc;
        __syncthreads();
        if (tid == 0) {
            float total = 0.0f;
#pragma unroll
            for (int k = 0; k < THREADS / 32; k++) total += warp_sum[k];
            out[0] = total * (1.0f / NPIX);
            g_done = 0;                  // reset for next graph replay
        }
    }
}

extern "C" void kernel_launch(void* const* d_in, const int* in_sizes, int n_in,
                              void* d_out, int out_size)
{
    const float* samples = (const float*)d_in[0];
    const float* target  = (const float*)d_in[1];
    crps_fused_kernel<<<BLOCKS, THREADS>>>(samples, target, (float*)d_out);
}

// round 4
// speedup vs baseline: 2.3463x; 1.1522x over previous
#include <cuda_runtime.h>
#include <cstdint>

// CRPS loss, fused single kernel, packed f32x2 math (sm_103a).
//   term1 = mean_i |s_i - y|
//   term2 = sum_{i<j} |s_i - s_j| / 256
//   out   = mean over pixels (term1 - term2)
//
// samples: [16, 4, 1, 256, 256] f32 -> 16 planes of 262144 floats
// target:  [4, 1, 256, 256]     f32 -> 262144 floats
// Each thread processes 2 adjacent pixels as one packed f32x2 lane pair.

#define NS      16
#define NPIX    (4 * 1 * 256 * 256)     // 262144
#define THREADS 256
#define PIX_PER_THREAD 2
#define BLOCKS  (NPIX / (THREADS * PIX_PER_THREAD))   // 512

__device__ float        g_partial[BLOCKS];
__device__ unsigned int g_done = 0;

// ---- packed f32x2 helpers (Blackwell-only; ptxas never auto-emits these) ----
__device__ __forceinline__ uint64_t fadd2(uint64_t a, uint64_t b) {
    uint64_t r; asm("add.rn.f32x2 %0, %1, %2;" : "=l"(r) : "l"(a), "l"(b)); return r;
}
__device__ __forceinline__ uint64_t ffma2(uint64_t a, uint64_t b, uint64_t c) {
    uint64_t r; asm("fma.rn.f32x2 %0, %1, %2, %3;" : "=l"(r) : "l"(a), "l"(b), "l"(c)); return r;
}
__device__ __forceinline__ uint64_t fabs2(uint64_t a) {
    return a & 0x7FFFFFFF7FFFFFFFULL;    // clear both sign bits (alu pipe LOP)
}
__device__ __forceinline__ uint64_t pack2(float2 v) {
    uint64_t r; asm("mov.b64 %0, {%1, %2};" : "=l"(r) : "f"(v.x), "f"(v.y)); return r;
}
__device__ __forceinline__ float2 unpack2(uint64_t v) {
    float lo, hi; asm("mov.b64 {%0, %1}, %2;" : "=f"(lo), "=f"(hi) : "l"(v));
    return make_float2(lo, hi);
}

#define NEG_ONE2 0xBF800000BF800000ULL   // {-1.0f, -1.0f}

__global__ __launch_bounds__(THREADS) void crps_fused_kernel(
    const float* __restrict__ samples,
    const float* __restrict__ target,
    float* __restrict__ out)
{
    const int tid = threadIdx.x;
    const int v   = blockIdx.x * THREADS + tid;      // float2 index (2 pixels)

    // ---- loads: 16 sample pairs + target pair, all LDG.64 coalesced ----
    uint64_t s[NS];
#pragma unroll
    for (int i = 0; i < NS; i++)
        s[i] = pack2(reinterpret_cast<const float2*>(samples + (size_t)i * NPIX)[v]);
    const uint64_t y = pack2(reinterpret_cast<const float2*>(target)[v]);

    // ---- term1: sum_i |s_i - y|, 2 packed accumulators ----
    uint64_t t1a = 0, t1b = 0;
#pragma unroll
    for (int i = 0; i < NS; i += 2) {
        t1a = fadd2(t1a, fabs2(ffma2(y, NEG_ONE2, s[i])));      // |s_i - y|
        t1b = fadd2(t1b, fabs2(ffma2(y, NEG_ONE2, s[i + 1])));
    }

    // ---- term2: sum_{i<j} |s_i - s_j|, 4 packed accumulators ----
    uint64_t t2[4] = {0, 0, 0, 0};
    {
        int c = 0;
#pragma unroll
        for (int i = 0; i < NS; i++) {
#pragma unroll
            for (int j = i + 1; j < NS; j++) {
                t2[c & 3] = fadd2(t2[c & 3], fabs2(ffma2(s[j], NEG_ONE2, s[i])));
                c++;
            }
        }
    }

    const float2 p1 = unpack2(fadd2(t1a, t1b));
    const float2 p2 = unpack2(fadd2(fadd2(t2[0], t2[1]), fadd2(t2[2], t2[3])));
    float val = (p1.x + p1.y) * (1.0f / NS)
              - (p2.x + p2.y) * (1.0f / (NS * NS));

    // ---- block reduction ----
    __shared__ float warp_sum[THREADS / 32];
    float w = val;
#pragma unroll
    for (int off = 16; off > 0; off >>= 1)
        w += __shfl_down_sync(0xFFFFFFFFu, w, off);
    if ((tid & 31) == 0) warp_sum[tid >> 5] = w;
    __syncthreads();

    __shared__ bool is_last;
    if (tid == 0) {
        float b = 0.0f;
#pragma unroll
        for (int k = 0; k < THREADS / 32; k++) b += warp_sum[k];
        g_partial[blockIdx.x] = b;
        __threadfence();
        unsigned int ticket = atomicAdd(&g_done, 1u);
        is_last = (ticket == BLOCKS - 1);
    }
    __syncthreads();

    // ---- last block folds partials, writes scalar, resets counter ----
    if (is_last) {
        float acc = 0.0f;
#pragma unroll
        for (int k = 0; k < BLOCKS / THREADS; k++)
            acc += g_partial[tid + k * THREADS];
#pragma unroll
        for (int off = 16; off > 0; off >>= 1)
            acc += __shfl_down_sync(0xFFFFFFFFu, acc, off);
        if ((tid & 31) == 0) warp_sum[tid >> 5] = acc;
        __syncthreads();
        if (tid == 0) {
            float total = 0.0f;
#pragma unroll
            for (int k = 0; k < THREADS / 32; k++) total += warp_sum[k];
            out[0] = total * (1.0f / NPIX);
            g_done = 0;
        }
    }
}

extern "C" void kernel_launch(void* const* d_in, const int* in_sizes, int n_in,
                              void* d_out, int out_size)
{
    const float* samples = (const float*)d_in[0];
    const float* target  = (const float*)d_in[1];
    crps_fused_kernel<<<BLOCKS, THREADS>>>(samples, target, (float*)d_out);
}